// round 9
// baseline (speedup 1.0000x reference)
#include <cuda_runtime.h>

// Shapes: re, gt are (B=32, C=10, H=192, W=320) float32, contiguous.
#define NB     32
#define NC     10
#define HW4    15360                  // (192*320)/4 float4 groups per channel
#define N4     (NB*HW4)               // 491520 groups total
#define BLK    256
#define GRID   (N4/BLK)               // 1920 blocks, 1 group per thread
#define NACC   6
#define EPSF   6e-8f

// [0]=nv [1]=num_pos [2]=focal_sum
// [3]=A (pos+height+const) [4]=B (len1+trig1) [5]=C (len2+trig2)
__device__ float g_part[NACC][GRID];
__device__ unsigned int g_count = 0;   // reset by last block each launch

__device__ __forceinline__ float sl1(float d) {
    float ad = fabsf(d);
    return ad < 1.0f ? 0.5f * d * d : ad - 0.5f;
}

__device__ __forceinline__ float c4(const float4& v, int j) {
    return j == 0 ? v.x : (j == 1 ? v.y : (j == 2 ? v.z : v.w));
}

// Streaming load (no reuse): LDG.E.128 with .cs policy.
__device__ __forceinline__ float4 ldcs4(const float4* p) {
    return __ldcs(p);
}

__global__ void __launch_bounds__(BLK, 6)
loss_kernel(const float* __restrict__ re, const float* __restrict__ gt,
            float* __restrict__ out) {
    float a_nv = 0.f, a_np = 0.f, a_f = 0.f, a_A = 0.f, a_B = 0.f, a_C = 0.f;

    const float4* __restrict__ re4 = (const float4*)re;
    const float4* __restrict__ gt4 = (const float4*)gt;

    const int i   = blockIdx.x * BLK + threadIdx.x;   // group index, < N4
    const int b   = i / HW4;
    const int hw4 = i - b * HW4;
    const int bs  = b * (NC * HW4) + hw4;             // float4 idx of (b,0,hw)

    // ---- channel 0: mask + focal ----
    const float4 G0 = ldcs4(gt4 + bs);
    const float4 R0 = ldcs4(re4 + bs);

    float mvf[4];
#pragma unroll
    for (int j = 0; j < 4; j++) {
        const float g = c4(G0, j);
        const float r = c4(R0, j);
        const bool  m0  = (g >= 0.0f);
        const bool  pos = (g >= 0.1f);              // FOCAL_THR, implies m0
        const float safe = fminf(fmaxf(r, 1e-6f), 1.0f - 1e-6f);
        const float larg = pos ? (safe + EPSF) : (1.0f + EPSF - safe);
        const float lg   = __logf(larg);            // larg > 0 always
        const float d0   = g - r;
        const float om   = 1.0f - g;
        const float om2  = om * om;
        float w = pos ? (d0 * d0) : (r * r * (om2 * om2));
        if (!m0) w = 0.0f;
        a_f -= w * lg;
        if (pos) a_np += 1.0f;
        mvf[j] = (g == 1.0f) ? 1.0f : 0.0f;
        a_nv += mvf[j];
    }

    // ---- channels 1,2 (pos, 0.5 = POS_W/2) and 9 (height, 0.1 = LEN_W) ----
    {
        const float4 R1 = ldcs4(re4 + bs + 1*HW4), G1 = ldcs4(gt4 + bs + 1*HW4);
        const float4 R2 = ldcs4(re4 + bs + 2*HW4), G2 = ldcs4(gt4 + bs + 2*HW4);
        const float4 R9 = ldcs4(re4 + bs + 9*HW4), G9 = ldcs4(gt4 + bs + 9*HW4);
#pragma unroll
        for (int j = 0; j < 4; j++) {
            a_A += mvf[j] * (0.5f * (sl1(c4(R1,j) - c4(G1,j))
                                   + sl1(c4(R2,j) - c4(G2,j)))
                           + 0.1f * sl1(c4(R9,j) - c4(G9,j)));
        }
    }

    // ---- channels 3,6 (length straight/crossed, 0.05 = LEN_W/2) ----
    {
        const float4 R3 = ldcs4(re4 + bs + 3*HW4), G3 = ldcs4(gt4 + bs + 3*HW4);
        const float4 R6 = ldcs4(re4 + bs + 6*HW4), G6 = ldcs4(gt4 + bs + 6*HW4);
#pragma unroll
        for (int j = 0; j < 4; j++) {
            const float r3 = c4(R3,j), g3 = c4(G3,j);
            const float r6 = c4(R6,j), g6 = c4(G6,j);
            a_B += mvf[j] * 0.05f * (sl1(r3 - g3) + sl1(r6 - g6));
            a_C += mvf[j] * 0.05f * (sl1(r3 - g6) + sl1(r6 - g3));
        }
    }

    // ---- channels 4,5,7,8 (trig 0.5 = TRIG_W/2, const 0.5 = CONST_W) ----
    {
        const float4 R4 = ldcs4(re4 + bs + 4*HW4), G4 = ldcs4(gt4 + bs + 4*HW4);
        const float4 R5 = ldcs4(re4 + bs + 5*HW4), G5 = ldcs4(gt4 + bs + 5*HW4);
        const float4 R7 = ldcs4(re4 + bs + 7*HW4), G7 = ldcs4(gt4 + bs + 7*HW4);
        const float4 R8 = ldcs4(re4 + bs + 8*HW4), G8 = ldcs4(gt4 + bs + 8*HW4);
#pragma unroll
        for (int j = 0; j < 4; j++) {
            const float r4 = c4(R4,j), g4 = c4(G4,j);
            const float r5 = c4(R5,j), g5 = c4(G5,j);
            const float r7 = c4(R7,j), g7 = c4(G7,j);
            const float r8 = c4(R8,j), g8 = c4(G8,j);
            const float d44 = r4 - g4, d77 = r7 - g7;
            const float d55 = r5 - g5, d88 = r8 - g8;
            a_B += mvf[j] * 0.5f * (d44*d44 + d77*d77 + d55*d55 + d88*d88);
            const float d47 = r4 - g7, d74 = r7 - g4;
            const float d58 = r5 - g8, d85 = r8 - g5;
            a_C += mvf[j] * 0.5f * (d47*d47 + d74*d74 + d58*d58 + d85*d85);
            const float c1 = 1.0f - r5*r5 - r4*r4;
            const float c2 = 1.0f - r8*r8 - r7*r7;
            a_A += mvf[j] * 0.5f * (c1*c1 + c2*c2);
        }
    }

    // Block reduction: warp shuffle -> shared -> per-block partial slot.
    float acc[NACC] = {a_nv, a_np, a_f, a_A, a_B, a_C};
    __shared__ float sh[BLK/32][NACC];
    const int lane = threadIdx.x & 31;
    const int warp = threadIdx.x >> 5;
#pragma unroll
    for (int k = 0; k < NACC; k++) {
        float v = acc[k];
#pragma unroll
        for (int o = 16; o > 0; o >>= 1)
            v += __shfl_down_sync(0xffffffffu, v, o);
        if (lane == 0) sh[warp][k] = v;
    }
    __syncthreads();
    if (threadIdx.x < NACC) {
        float v = 0.0f;
#pragma unroll
        for (int w = 0; w < BLK/32; w++) v += sh[w][threadIdx.x];
        g_part[threadIdx.x][blockIdx.x] = v;
    }

    // Last-block-done: the final block to arrive reduces all partials.
    __shared__ bool is_last;
    __threadfence();
    __syncthreads();
    if (threadIdx.x == 0) {
        unsigned int old = atomicAdd(&g_count, 1u);
        is_last = (old == GRID - 1);
    }
    __syncthreads();
    if (!is_last) return;

    __threadfence();   // ensure we see every block's partials

    // 6 warps reduce the 6 accumulators over all 1920 block partials.
    __shared__ float tot[NACC];
    if (warp < NACC) {
        float v = 0.0f;
        for (int j = lane; j < GRID; j += 32) v += g_part[warp][j];
#pragma unroll
        for (int o = 16; o > 0; o >>= 1)
            v += __shfl_down_sync(0xffffffffu, v, o);
        if (lane == 0) tot[warp] = v;
    }
    __syncthreads();

    if (threadIdx.x == 0) {
        g_count = 0;   // reset for next graph replay

        const float nv      = tot[0];
        const float num_pos = tot[1];
        const float S       = tot[2];
        const float focal = (num_pos == 0.0f) ? S : S / num_pos;
        out[0] = focal + (tot[3] + fminf(tot[4], tot[5])) / nv;
    }
}

extern "C" void kernel_launch(void* const* d_in, const int* in_sizes, int n_in,
                              void* d_out, int out_size) {
    const float* re = (const float*)d_in[0];
    const float* gt = (const float*)d_in[1];
    float* out = (float*)d_out;

    loss_kernel<<<GRID, BLK>>>(re, gt, out);
}

// round 10
// speedup vs baseline: 1.0632x; 1.0632x over previous
#include <cuda_runtime.h>

// Shapes: re, gt are (B=32, C=10, H=192, W=320) float32, contiguous.
#define NB     32
#define NC     10
#define HW4    15360                  // (192*320)/4 float4 groups per channel
#define N4     (NB*HW4)               // 491520 groups total
#define BLK    256
#define HALF   128                    // groups per block (each covered by 2 roles)
#define GRID   (N4/HALF)              // 3840 blocks
#define NACC   6
#define EPSF   6e-8f

// [0]=nv [1]=num_pos [2]=focal_sum
// [3]=A (pos+height+const) [4]=B (len1+trig1) [5]=C (len2+trig2)
__device__ float g_part[NACC][GRID];
__device__ unsigned int g_count = 0;   // reset by last block each launch

__device__ __forceinline__ float sl1(float d) {
    float ad = fabsf(d);
    return ad < 1.0f ? 0.5f * d * d : ad - 0.5f;
}

__device__ __forceinline__ float c4(const float4& v, int j) {
    return j == 0 ? v.x : (j == 1 ? v.y : (j == 2 ? v.z : v.w));
}

__global__ void __launch_bounds__(BLK, 4)
loss_kernel(const float* __restrict__ re, const float* __restrict__ gt,
            float* __restrict__ out) {
    float a_nv = 0.f, a_np = 0.f, a_f = 0.f, a_A = 0.f, a_B = 0.f, a_C = 0.f;

    const float4* __restrict__ re4 = (const float4*)re;
    const float4* __restrict__ gt4 = (const float4*)gt;

    const int tid = threadIdx.x;
    const int grp = blockIdx.x * HALF + (tid & (HALF - 1)); // group index < N4
    const int b   = grp / HW4;
    const int hw4 = grp - b * HW4;
    const int bs  = b * (NC * HW4) + hw4;   // float4 idx of (b,0,hw)

    if (tid < HALF) {
        // ---- Role A: ch0 focal/mask + pos(1,2) + length(3,6) : 10 streams ----
        const float4 G0 = gt4[bs        ], R0 = re4[bs        ];
        const float4 G1 = gt4[bs + 1*HW4], R1 = re4[bs + 1*HW4];
        const float4 G2 = gt4[bs + 2*HW4], R2 = re4[bs + 2*HW4];
        const float4 G3 = gt4[bs + 3*HW4], R3 = re4[bs + 3*HW4];
        const float4 G6 = gt4[bs + 6*HW4], R6 = re4[bs + 6*HW4];

#pragma unroll
        for (int j = 0; j < 4; j++) {
            const float g = c4(G0, j);
            const float r = c4(R0, j);
            const bool  m0  = (g >= 0.0f);
            const bool  pos = (g >= 0.1f);          // FOCAL_THR, implies m0
            const float safe = fminf(fmaxf(r, 1e-6f), 1.0f - 1e-6f);
            const float larg = pos ? (safe + EPSF) : (1.0f + EPSF - safe);
            const float lg   = __logf(larg);        // larg > 0 always
            const float d0   = g - r;
            const float om   = 1.0f - g;
            const float om2  = om * om;
            float w = pos ? (d0 * d0) : (r * r * (om2 * om2));
            if (!m0) w = 0.0f;
            a_f -= w * lg;
            if (pos) a_np += 1.0f;

            const float mvf = (g == 1.0f) ? 1.0f : 0.0f;
            a_nv += mvf;                            // counted once (role A only)

            // pos (0.5 = POS_W/2)
            a_A += mvf * 0.5f * (sl1(c4(R1,j) - c4(G1,j))
                               + sl1(c4(R2,j) - c4(G2,j)));
            // length straight/crossed (0.05 = LEN_W/2)
            const float r3 = c4(R3,j), g3 = c4(G3,j);
            const float r6 = c4(R6,j), g6 = c4(G6,j);
            a_B += mvf * 0.05f * (sl1(r3 - g3) + sl1(r6 - g6));
            a_C += mvf * 0.05f * (sl1(r3 - g6) + sl1(r6 - g3));
        }
    } else {
        // ---- Role B: ch0 mask + trig/const(4,5,7,8) + height(9) : 11 streams ----
        const float4 G0 = gt4[bs        ];
        const float4 G4 = gt4[bs + 4*HW4], R4 = re4[bs + 4*HW4];
        const float4 G5 = gt4[bs + 5*HW4], R5 = re4[bs + 5*HW4];
        const float4 G7 = gt4[bs + 7*HW4], R7 = re4[bs + 7*HW4];
        const float4 G8 = gt4[bs + 8*HW4], R8 = re4[bs + 8*HW4];
        const float4 G9 = gt4[bs + 9*HW4], R9 = re4[bs + 9*HW4];

#pragma unroll
        for (int j = 0; j < 4; j++) {
            const float mvf = (c4(G0, j) == 1.0f) ? 1.0f : 0.0f;

            const float r4 = c4(R4,j), g4 = c4(G4,j);
            const float r5 = c4(R5,j), g5 = c4(G5,j);
            const float r7 = c4(R7,j), g7 = c4(G7,j);
            const float r8 = c4(R8,j), g8 = c4(G8,j);

            // trig (0.5 = TRIG_W/2)
            const float d44 = r4 - g4, d77 = r7 - g7;
            const float d55 = r5 - g5, d88 = r8 - g8;
            a_B += mvf * 0.5f * (d44*d44 + d77*d77 + d55*d55 + d88*d88);
            const float d47 = r4 - g7, d74 = r7 - g4;
            const float d58 = r5 - g8, d85 = r8 - g5;
            a_C += mvf * 0.5f * (d47*d47 + d74*d74 + d58*d58 + d85*d85);
            // const (0.5 = CONST_W) + height (0.1 = LEN_W)
            const float c1 = 1.0f - r5*r5 - r4*r4;
            const float c2 = 1.0f - r8*r8 - r7*r7;
            a_A += mvf * (0.5f * (c1*c1 + c2*c2)
                        + 0.1f * sl1(c4(R9,j) - c4(G9,j)));
        }
    }

    // Block reduction: warp shuffle -> shared -> per-block partial slot.
    float acc[NACC] = {a_nv, a_np, a_f, a_A, a_B, a_C};
    __shared__ float sh[BLK/32][NACC];
    const int lane = tid & 31;
    const int warp = tid >> 5;
#pragma unroll
    for (int k = 0; k < NACC; k++) {
        float v = acc[k];
#pragma unroll
        for (int o = 16; o > 0; o >>= 1)
            v += __shfl_down_sync(0xffffffffu, v, o);
        if (lane == 0) sh[warp][k] = v;
    }
    __syncthreads();
    if (tid < NACC) {
        float v = 0.0f;
#pragma unroll
        for (int w = 0; w < BLK/32; w++) v += sh[w][tid];
        g_part[tid][blockIdx.x] = v;
    }

    // Last-block-done: the final block to arrive reduces all partials.
    __shared__ bool is_last;
    __threadfence();
    __syncthreads();
    if (tid == 0) {
        unsigned int old = atomicAdd(&g_count, 1u);
        is_last = (old == GRID - 1);
    }
    __syncthreads();
    if (!is_last) return;

    __threadfence();   // ensure we see every block's partials

    // 6 warps reduce the 6 accumulators over all 3840 block partials.
    __shared__ float tot[NACC];
    if (warp < NACC) {
        float v = 0.0f;
        for (int j = lane; j < GRID; j += 32) v += g_part[warp][j];
#pragma unroll
        for (int o = 16; o > 0; o >>= 1)
            v += __shfl_down_sync(0xffffffffu, v, o);
        if (lane == 0) tot[warp] = v;
    }
    __syncthreads();

    if (tid == 0) {
        g_count = 0;   // reset for next graph replay

        const float nv      = tot[0];
        const float num_pos = tot[1];
        const float S       = tot[2];
        const float focal = (num_pos == 0.0f) ? S : S / num_pos;
        out[0] = focal + (tot[3] + fminf(tot[4], tot[5])) / nv;
    }
}

extern "C" void kernel_launch(void* const* d_in, const int* in_sizes, int n_in,
                              void* d_out, int out_size) {
    const float* re = (const float*)d_in[0];
    const float* gt = (const float*)d_in[1];
    float* out = (float*)d_out;

    loss_kernel<<<GRID, BLK>>>(re, gt, out);
}

// round 11
// speedup vs baseline: 1.2607x; 1.1858x over previous
#include <cuda_runtime.h>

// Shapes: re, gt are (B=32, C=10, H=192, W=320) float32, contiguous.
#define NB     32
#define NC     10
#define HW4    15360                  // (192*320)/4 float4 groups per channel
#define N4     (NB*HW4)               // 491520 groups total
#define BLK    256
#define GPT    2                      // groups per thread
#define GRID   (N4/(BLK*GPT))         // 960 blocks
#define STRIDE (GRID*BLK)             // 245760
#define NACC   6
#define EPSF   6e-8f

// [0]=nv [1]=num_pos [2]=focal_sum
// [3]=A (pos+height+const) [4]=B (len1+trig1) [5]=C (len2+trig2)
__device__ float g_part[NACC][GRID];
__device__ unsigned int g_count = 0;   // reset by last block each launch

__device__ __forceinline__ float sl1(float d) {
    float ad = fabsf(d);
    return ad < 1.0f ? 0.5f * d * d : ad - 0.5f;
}

__device__ __forceinline__ float c4(const float4& v, int j) {
    return j == 0 ? v.x : (j == 1 ? v.y : (j == 2 ? v.z : v.w));
}

__global__ void
loss_kernel(const float* __restrict__ re, const float* __restrict__ gt,
            float* __restrict__ out) {
    float a_nv = 0.f, a_np = 0.f, a_f = 0.f, a_A = 0.f, a_B = 0.f, a_C = 0.f;

    const float4* __restrict__ re4 = (const float4*)re;
    const float4* __restrict__ gt4 = (const float4*)gt;

    const int t = blockIdx.x * BLK + threadIdx.x;

    // Both groups' channel-0 loads batched up front (one window, MLP=4).
    int base[GPT];
    float4 G0v[GPT], R0v[GPT];
#pragma unroll
    for (int it = 0; it < GPT; it++) {
        const int i   = t + it * STRIDE;
        const int b   = i / HW4;
        const int hw4 = i - b * HW4;
        base[it] = b * (NC * HW4) + hw4;
        G0v[it] = gt4[base[it]];
        R0v[it] = re4[base[it]];
    }

#pragma unroll
    for (int it = 0; it < GPT; it++) {
        const int bs = base[it];
        const float4 G0 = G0v[it];
        const float4 R0 = R0v[it];

        // ---- focal (branchless, single log) + mask ----
        float mvf[4];
        bool any = false;
#pragma unroll
        for (int j = 0; j < 4; j++) {
            const float g = c4(G0, j);
            const float r = c4(R0, j);
            const bool  m0  = (g >= 0.0f);
            const bool  pos = (g >= 0.1f);          // FOCAL_THR, implies m0
            const float safe = fminf(fmaxf(r, 1e-6f), 1.0f - 1e-6f);
            const float larg = pos ? (safe + EPSF) : (1.0f + EPSF - safe);
            const float lg   = __logf(larg);        // larg > 0 always
            const float d0   = g - r;
            const float om   = 1.0f - g;
            const float om2  = om * om;
            float w = pos ? (d0 * d0) : (r * r * (om2 * om2));
            if (!m0) w = 0.0f;
            a_f -= w * lg;
            if (pos) a_np += 1.0f;
            mvf[j] = (g == 1.0f) ? 1.0f : 0.0f;
            a_nv += mvf[j];
            any |= (mvf[j] != 0.0f);
        }

        if (any) {
            // All 18 remaining channel loads in ONE window (MLP=18).
            const float4 R1 = re4[bs + 1*HW4], G1 = gt4[bs + 1*HW4];
            const float4 R2 = re4[bs + 2*HW4], G2 = gt4[bs + 2*HW4];
            const float4 R3 = re4[bs + 3*HW4], G3 = gt4[bs + 3*HW4];
            const float4 R4 = re4[bs + 4*HW4], G4 = gt4[bs + 4*HW4];
            const float4 R5 = re4[bs + 5*HW4], G5 = gt4[bs + 5*HW4];
            const float4 R6 = re4[bs + 6*HW4], G6 = gt4[bs + 6*HW4];
            const float4 R7 = re4[bs + 7*HW4], G7 = gt4[bs + 7*HW4];
            const float4 R8 = re4[bs + 8*HW4], G8 = gt4[bs + 8*HW4];
            const float4 R9 = re4[bs + 9*HW4], G9 = gt4[bs + 9*HW4];

#pragma unroll
            for (int j = 0; j < 4; j++) {
                const float m = mvf[j];
                if (m == 0.0f) continue;

                // pos (0.5 = POS_W/2) + height (0.1 = LEN_W)
                a_A += m * (0.5f * (sl1(c4(R1,j) - c4(G1,j))
                                  + sl1(c4(R2,j) - c4(G2,j)))
                          + 0.1f * sl1(c4(R9,j) - c4(G9,j)));

                // length straight/crossed (0.05 = LEN_W/2)
                const float r3 = c4(R3,j), g3 = c4(G3,j);
                const float r6 = c4(R6,j), g6 = c4(G6,j);
                a_B += m * 0.05f * (sl1(r3 - g3) + sl1(r6 - g6));
                a_C += m * 0.05f * (sl1(r3 - g6) + sl1(r6 - g3));

                // trig (0.5 = TRIG_W/2) + const (0.5 = CONST_W)
                const float r4 = c4(R4,j), g4 = c4(G4,j);
                const float r5 = c4(R5,j), g5 = c4(G5,j);
                const float r7 = c4(R7,j), g7 = c4(G7,j);
                const float r8 = c4(R8,j), g8 = c4(G8,j);
                const float d44 = r4 - g4, d77 = r7 - g7;
                const float d55 = r5 - g5, d88 = r8 - g8;
                a_B += m * 0.5f * (d44*d44 + d77*d77 + d55*d55 + d88*d88);
                const float d47 = r4 - g7, d74 = r7 - g4;
                const float d58 = r5 - g8, d85 = r8 - g5;
                a_C += m * 0.5f * (d47*d47 + d74*d74 + d58*d58 + d85*d85);
                const float c1 = 1.0f - r5*r5 - r4*r4;
                const float c2 = 1.0f - r8*r8 - r7*r7;
                a_A += m * 0.5f * (c1*c1 + c2*c2);
            }
        }
    }

    // Block reduction: warp shuffle -> shared -> per-block partial slot.
    float acc[NACC] = {a_nv, a_np, a_f, a_A, a_B, a_C};
    __shared__ float sh[BLK/32][NACC];
    const int lane = threadIdx.x & 31;
    const int warp = threadIdx.x >> 5;
#pragma unroll
    for (int k = 0; k < NACC; k++) {
        float v = acc[k];
#pragma unroll
        for (int o = 16; o > 0; o >>= 1)
            v += __shfl_down_sync(0xffffffffu, v, o);
        if (lane == 0) sh[warp][k] = v;
    }
    __syncthreads();
    if (threadIdx.x < NACC) {
        float v = 0.0f;
#pragma unroll
        for (int w = 0; w < BLK/32; w++) v += sh[w][threadIdx.x];
        g_part[threadIdx.x][blockIdx.x] = v;
    }

    // Last-block-done: the final block to arrive reduces all partials.
    __shared__ bool is_last;
    __threadfence();
    __syncthreads();
    if (threadIdx.x == 0) {
        unsigned int old = atomicAdd(&g_count, 1u);
        is_last = (old == GRID - 1);
    }
    __syncthreads();
    if (!is_last) return;

    __threadfence();   // ensure we see every block's partials

    // 6 warps reduce the 6 accumulators over all 960 block partials.
    __shared__ float tot[NACC];
    if (warp < NACC) {
        float v = 0.0f;
        for (int j = lane; j < GRID; j += 32) v += g_part[warp][j];
#pragma unroll
        for (int o = 16; o > 0; o >>= 1)
            v += __shfl_down_sync(0xffffffffu, v, o);
        if (lane == 0) tot[warp] = v;
    }
    __syncthreads();

    if (threadIdx.x == 0) {
        g_count = 0;   // reset for next graph replay

        const float nv      = tot[0];
        const float num_pos = tot[1];
        const float S       = tot[2];
        const float focal = (num_pos == 0.0f) ? S : S / num_pos;
        out[0] = focal + (tot[3] + fminf(tot[4], tot[5])) / nv;
    }
}

extern "C" void kernel_launch(void* const* d_in, const int* in_sizes, int n_in,
                              void* d_out, int out_size) {
    const float* re = (const float*)d_in[0];
    const float* gt = (const float*)d_in[1];
    float* out = (float*)d_out;

    loss_kernel<<<GRID, BLK>>>(re, gt, out);
}